// round 16
// baseline (speedup 1.0000x reference)
#include <cuda_runtime.h>

#define NB 2
#define NH 16
#define NT 8192
#define ND 64
#define NM 8
#define NP 32                       // ND/2
#define BHTD (NB*NH*NT*ND)          // 33554432
#define TB 128                      // tokens per block
#define THREADS 128
#define CS_BLOCKS 1024              // 1024*256 = NT*NP threads

typedef unsigned long long u64;

// Scratch (allocation-free): normalized Householder vectors + cos/sin table
__device__ float  g_U[NH*NM*ND];    // 8192 floats
__device__ float2 g_cs[NT*NP];      // 2 MB, token row = 32 float2 = 16 float4

// ---------------- packed f32x2 helpers ----------------
__device__ __forceinline__ u64 pack2(float lo, float hi) {
    u64 r; asm("mov.b64 %0, {%1,%2};" : "=l"(r) : "f"(lo), "f"(hi)); return r;
}
__device__ __forceinline__ void unpack2(u64 a, float& lo, float& hi) {
    asm("mov.b64 {%0,%1}, %2;" : "=f"(lo), "=f"(hi) : "l"(a));
}
__device__ __forceinline__ u64 ffma2(u64 a, u64 b, u64 c) {
    u64 d; asm("fma.rn.f32x2 %0, %1, %2, %3;" : "=l"(d) : "l"(a), "l"(b), "l"(c));
    return d;
}

// ---------------- fused prep kernel ----------------
__global__ void prep(const float* __restrict__ V, const float* __restrict__ pos,
                     const float* __restrict__ freq)
{
    int b = blockIdx.x;
    if (b < CS_BLOCKS) {
        int idx = b*256 + threadIdx.x;       // 0 .. NT*NP-1
        int t = idx >> 5, p = idx & 31;
        float a = pos[t] * freq[p];
        float s, c;
        sincosf(a, &s, &c);
        g_cs[idx] = make_float2(c, s);
    } else {
        int rb = b - CS_BLOCKS;              // 0..15
        int w = threadIdx.x >> 5, l = threadIdx.x & 31;
        int row = rb*8 + w;                  // 0..127 (= NH*NM-1)
        float a  = V[row*ND + l];
        float bb = V[row*ND + 32 + l];
        float s = a*a + bb*bb;
        #pragma unroll
        for (int o = 16; o; o >>= 1) s += __shfl_xor_sync(0xffffffffu, s, o);
        float inv = rsqrtf(s + 1e-16f);      // EPS^2
        g_U[row*ND + l]      = a*inv;
        g_U[row*ND + 32 + l] = bb*inv;
    }
}

// ---------------- main kernel ----------------
// Block: 128 threads = 128 tokens. Thread owns BOTH the q-vector and k-vector of
// one token (64+64 floats as packed f32x2 in registers). Each broadcast U load
// feeds 2 dots + 2 updates; dot phase has 4 independent FFMA2 chains.
// smem rows pitch 17 float4 -> conflict-free LDS/STS.128 on both the coalesced
// (lanes vary row) and owner (lanes vary column) access patterns.
// RoPE fused into the coalesced output phase; cs via coalesced LDG.128 (L2-resident).

extern __shared__ float4 smem4[];

__global__ __launch_bounds__(THREADS, 3) void hh_rope(
    const float* __restrict__ q, const float* __restrict__ k, float* __restrict__ out)
{
    float4* zq = smem4;                 // 128*17 float4 = 34816 B
    float4* zk = zq + TB*17;            // 128*17 float4 = 34816 B
    float4* ub = zk + TB*17;            // 128 float4    =  2048 B

    const int tid = threadIdx.x;
    const int bx  = blockIdx.x;         // token tile (NT/TB = 64)
    const int by  = blockIdx.y;         // b*NH + h (32)
    const int h   = by & (NH-1);
    const int t0  = bx * TB;

    // Stage U for this head: 128 float4 (plain layout; hot-loop reads are broadcasts)
    ub[tid] = ((const float4*)g_U)[(size_t)h*128 + tid];

    // Stage q,k tiles: 2048 float4 each, coalesced LDG.128 -> padded STS.128
    const size_t base = ((size_t)by*NT + t0) * (ND/4);   // float4 index
    const float4* qb = (const float4*)q + base;
    const float4* kb = (const float4*)k + base;
    #pragma unroll
    for (int i = 0; i < 16; i++) {
        int f = i*THREADS + tid;        // 0..2047
        int v = f >> 4, j = f & 15;
        zq[v*17 + j] = qb[f];
    }
    #pragma unroll
    for (int i = 0; i < 16; i++) {
        int f = i*THREADS + tid;
        int v = f >> 4, j = f & 15;
        zk[v*17 + j] = kb[f];
    }
    __syncthreads();

    // Pull own token's q and k vectors into packed registers (owner path, conflict-free)
    u64 zzq[32], zzk[32];
    {
        const ulonglong2* rq = (const ulonglong2*)(zq + tid*17);
        const ulonglong2* rk = (const ulonglong2*)(zk + tid*17);
        #pragma unroll
        for (int j = 0; j < 16; j++) {
            ulonglong2 a = rq[j]; zzq[2*j] = a.x; zzq[2*j+1] = a.y;
            ulonglong2 b = rk[j]; zzk[2*j] = b.x; zzk[2*j+1] = b.y;
        }
    }

    // 8 Householder reflections, m = 7..0 (matches reference). One broadcast U load
    // per float4 serves q-dot, k-dot (and re-loaded once for both updates).
    #pragma unroll 1
    for (int m = NM - 1; m >= 0; m--) {
        const ulonglong2* uv = (const ulonglong2*)(ub + m*16);
        u64 aq0 = 0ull, aq1 = 0ull, ak0 = 0ull, ak1 = 0ull;
        #pragma unroll 4
        for (int j = 0; j < 16; j++) {
            ulonglong2 u = uv[j];
            aq0 = ffma2(zzq[2*j],   u.x, aq0);
            aq1 = ffma2(zzq[2*j+1], u.y, aq1);
            ak0 = ffma2(zzk[2*j],   u.x, ak0);
            ak1 = ffma2(zzk[2*j+1], u.y, ak1);
        }
        float q0, q1, q2, q3, k0, k1, k2, k3;
        unpack2(aq0, q0, q1); unpack2(aq1, q2, q3);
        unpack2(ak0, k0, k1); unpack2(ak1, k2, k3);
        float cq = -2.0f * ((q0 + q1) + (q2 + q3));
        float ck = -2.0f * ((k0 + k1) + (k2 + k3));
        u64 ccq = pack2(cq, cq);
        u64 cck = pack2(ck, ck);
        #pragma unroll 4
        for (int j = 0; j < 16; j++) {
            ulonglong2 u = uv[j];
            zzq[2*j]   = ffma2(ccq, u.x, zzq[2*j]);
            zzq[2*j+1] = ffma2(ccq, u.y, zzq[2*j+1]);
            zzk[2*j]   = ffma2(cck, u.x, zzk[2*j]);
            zzk[2*j+1] = ffma2(cck, u.y, zzk[2*j+1]);
        }
    }

    // Write reflected vectors back to own rows (exclusive, conflict-free)
    {
        ulonglong2* rq = (ulonglong2*)(zq + tid*17);
        ulonglong2* rk = (ulonglong2*)(zk + tid*17);
        #pragma unroll
        for (int j = 0; j < 16; j++) {
            rq[j] = make_ulonglong2(zzq[2*j], zzq[2*j+1]);
            rk[j] = make_ulonglong2(zzk[2*j], zzk[2*j+1]);
        }
    }
    __syncthreads();

    // Output phase with fused RoPE. zbuf read coalesced; cs read as coalesced
    // LDG.128 (16 lanes cover one token's contiguous 256B cs row; L2-resident).
    const float4* cs4 = (const float4*)g_cs;    // token row = 16 float4
    float4* oq = (float4*)out + base;
    float4* ok = (float4*)out + (size_t)(BHTD/4) + base;
    #pragma unroll
    for (int i = 0; i < 16; i++) {
        int f = i*THREADS + tid;
        int v = f >> 4, j = f & 15;
        float4 z  = zq[v*17 + j];
        float4 cp = cs4[(size_t)(t0 + v)*16 + j];    // (c0,s0,c1,s1)
        float4 r;
        r.x = fmaf(z.x, cp.x, -(z.y*cp.y));
        r.y = fmaf(z.x, cp.y,   z.y*cp.x);
        r.z = fmaf(z.z, cp.z, -(z.w*cp.w));
        r.w = fmaf(z.z, cp.w,   z.w*cp.z);
        oq[f] = r;
    }
    #pragma unroll
    for (int i = 0; i < 16; i++) {
        int f = i*THREADS + tid;
        int v = f >> 4, j = f & 15;
        float4 z  = zk[v*17 + j];
        float4 cp = cs4[(size_t)(t0 + v)*16 + j];
        float4 r;
        r.x = fmaf(z.x, cp.x, -(z.y*cp.y));
        r.y = fmaf(z.x, cp.y,   z.y*cp.x);
        r.z = fmaf(z.z, cp.z, -(z.w*cp.w));
        r.w = fmaf(z.z, cp.w,   z.w*cp.z);
        ok[f] = r;
    }
}

// ---------------- launch ----------------

extern "C" void kernel_launch(void* const* d_in, const int* in_sizes, int n_in,
                              void* d_out, int out_size) {
    const float* q    = (const float*)d_in[0];
    const float* k    = (const float*)d_in[1];
    const float* V    = (const float*)d_in[2];
    const float* pos  = (const float*)d_in[3];
    const float* freq = (const float*)d_in[4];
    float* out = (float*)d_out;

    const int smem_bytes = (TB*17*2 + 128) * 16;   // 71680
    cudaFuncSetAttribute(hh_rope, cudaFuncAttributeMaxDynamicSharedMemorySize, smem_bytes);

    prep<<<CS_BLOCKS + 16, 256>>>(V, pos, freq);

    dim3 grid(NT/TB, NB*NH);
    hh_rope<<<grid, THREADS, smem_bytes>>>(q, k, out);
}